// round 7
// baseline (speedup 1.0000x reference)
#include <cuda_runtime.h>
#include <cuda_pipeline.h>
#include <math.h>
#include <float.h>

// MultiScaleDynamicFusionGate — GB300 sm_103a — R7
// R6 + (a) exact wait_prior counts (R6 read the last chunk without waiting —
// rel_err 5e-5 was a real race), (b) 3-stage per-warp cp.async pipeline so
// TWO chunks are in flight while reducing one (R6's depth-1 left the warp
// latency-exposed at each wait; DRAM capped at 69%).

#define L_DIM 1024

extern __shared__ float stage_smem[];   // [8 warps][3 stages][1024 floats] = 96KB

__global__ __launch_bounds__(256) void msdfg_kernel(
    const float* __restrict__ a1, const float* __restrict__ a2,
    const float* __restrict__ W1, const float* __restrict__ b1,
    const float* __restrict__ W2, const float* __restrict__ b2,
    const float* __restrict__ W3, const float* __restrict__ b3,
    const float* __restrict__ sw, float* __restrict__ out)
{
    __shared__ float shW1T[3][8][32];    // [s][f][o]
    __shared__ float shB1[3][32];
    __shared__ float shW2T[3][32][16];   // [s][f][o]
    __shared__ float shB2[3][16];
    __shared__ float shW3[3][16];
    __shared__ float shB3[3];
    __shared__ float shSW[3];
    __shared__ float rs[8][8][8];        // [warp][row][stat]

    const int tid  = threadIdx.x;
    const int w    = tid >> 5;
    const int lane = tid & 31;

    // ---- One-time weight staging ----
    for (int idx = tid; idx < 768; idx += 256) {          // W1 [3][32][8]
        int s = idx >> 8, rem = idx & 255;
        shW1T[s][rem & 7][rem >> 3] = W1[idx];
    }
    for (int idx = tid; idx < 1536; idx += 256) {         // W2 [3][16][32]
        int s = idx >> 9, rem = idx & 511;
        shW2T[s][rem & 31][rem >> 5] = W2[idx];
    }
    if (tid < 96)                 ((float*)shB1)[tid] = b1[tid];
    else if (tid < 144)           ((float*)shB2)[tid - 96]  = b2[tid - 96];
    else if (tid < 192)           ((float*)shW3)[tid - 144] = W3[tid - 144];
    else if (tid < 195)           ((float*)shB3)[tid - 192] = b3[tid - 192];
    else if (tid >= 200 && tid < 203) shSW[tid - 200] = sw[tid - 200];
    __syncthreads();

    const int group = blockIdx.x * 8 + w;                 // 8192 groups
    const long long row0 = (long long)group * 8;

    const float invL  = 1.0f / (float)L_DIM;
    const float invN1 = 1.0f / (float)(L_DIM - 1);

    float* stg = stage_smem + w * 3072;   // this warp's three 1024-float stages

    // Chunk c (0..15): row = c>>1, tensor = c&1. 4KB per chunk.
    // Stage for chunk c is (c % 3). Lane j copies/reads float4 j, j+32, ..., j+224.

    // ---- Prologue: issue chunks 0,1,2 ----
    #pragma unroll
    for (int c = 0; c < 3; c++) {
        const float* base = (c & 1) ? a2 : a1;
        const float4* s4 = (const float4*)(base + (row0 + (c >> 1)) * (long long)L_DIM);
        float4* d4 = (float4*)(stg + (c % 3) * 1024);
        #pragma unroll
        for (int i = 0; i < 8; i++)
            __pipeline_memcpy_async(&d4[lane + 32 * i], &s4[lane + 32 * i], 16);
        __pipeline_commit();
    }

    // ---- Main pipeline: wait chunk c, reduce it, issue chunk c+3 ----
    #pragma unroll
    for (int c = 0; c < 16; c++) {
        // commits so far = min(c+3,16); groups pending after chunk c completes:
        //   c <= 13 -> 2, c == 14 -> 1, c == 15 -> 0   (all compile-time)
        if (c <= 13)      __pipeline_wait_prior(2);
        else if (c == 14) __pipeline_wait_prior(1);
        else              __pipeline_wait_prior(0);

        const float4* d4 = (const float4*)(stg + (c % 3) * 1024);
        float sa = 0.f, sb = 0.f, qa = 0.f, qb = 0.f;
        float mx = -FLT_MAX, mn = FLT_MAX;
        #pragma unroll
        for (int i = 0; i < 8; i++) {
            float4 v = d4[lane + 32 * i];
            if (i & 1) { sb += (v.x + v.y) + (v.z + v.w);
                         qb += (v.x * v.x + v.y * v.y) + (v.z * v.z + v.w * v.w); }
            else       { sa += (v.x + v.y) + (v.z + v.w);
                         qa += (v.x * v.x + v.y * v.y) + (v.z * v.z + v.w * v.w); }
            mx = fmaxf(mx, fmaxf(fmaxf(v.x, v.y), fmaxf(v.z, v.w)));
            mn = fminf(mn, fminf(fminf(v.x, v.y), fminf(v.z, v.w)));
        }

        // Refill this stage with chunk c+3 (lane-private region, no hazard).
        if (c + 3 < 16) {
            int cn = c + 3;
            const float* base = (cn & 1) ? a2 : a1;
            const float4* s4 = (const float4*)(base + (row0 + (cn >> 1)) * (long long)L_DIM);
            float4* dn = (float4*)(stg + (cn % 3) * 1024);
            #pragma unroll
            for (int i = 0; i < 8; i++)
                __pipeline_memcpy_async(&dn[lane + 32 * i], &s4[lane + 32 * i], 16);
            __pipeline_commit();
        }

        // Warp reduce (two chunks remain in flight during this).
        float s = sa + sb, q = qa + qb;
        #pragma unroll
        for (int off = 16; off > 0; off >>= 1) {
            s  += __shfl_xor_sync(0xffffffffu, s, off);
            q  += __shfl_xor_sync(0xffffffffu, q, off);
            mx  = fmaxf(mx, __shfl_xor_sync(0xffffffffu, mx, off));
            mn  = fminf(mn, __shfl_xor_sync(0xffffffffu, mn, off));
        }
        if (lane == 0) {
            const int r = c >> 1, t = (c & 1) * 4;
            rs[w][r][t + 0] = s;
            rs[w][r][t + 1] = sqrtf(fmaxf(0.f, (q - s * s * invL) * invN1));
            rs[w][r][t + 2] = mx;
            rs[w][r][t + 3] = mn;
        }
    }
    __syncwarp();

    // ---- Softmax over scale_weights ----
    float w0, w1g, w2g;
    {
        float t0 = shSW[0], t1 = shSW[1], t2 = shSW[2];
        float m  = fmaxf(t0, fmaxf(t1, t2));
        float e0 = __expf(t0 - m), e1 = __expf(t1 - m), e2 = __expf(t2 - m);
        float inv = 1.0f / (e0 + e1 + e2);
        w0 = e0 * inv; w1g = e1 * inv; w2g = e2 * inv;   // ws=2, ws=4, ws=8
    }

    // ---- Phase 2: 7 windows, lane-parallel MLPs ----
    float acc = 0.f;

    #pragma unroll
    for (int wi = 0; wi < 7; wi++) {
        int s, ws, r0;
        float wgt;
        if (wi == 0)      { s = 2; ws = 8; r0 = 0;            wgt = w2g; }
        else if (wi < 3)  { s = 1; ws = 4; r0 = (wi - 1) * 4; wgt = w1g; }
        else              { s = 0; ws = 2; r0 = (wi - 3) * 2; wgt = w0;  }

        const float invws = 1.0f / (float)ws;

        float g[8];
        {
            float sm1 = 0.f, sd1 = 0.f, sx1 = 0.f, sn1 = 0.f;
            float sm2 = 0.f, sd2 = 0.f, sx2 = 0.f, sn2 = 0.f;
            #pragma unroll
            for (int r = 0; r < 8; r++) {
                if (r >= r0 && r < r0 + ws) {
                    sm1 += rs[w][r][0]; sd1 += rs[w][r][1];
                    sx1 += rs[w][r][2]; sn1 += rs[w][r][3];
                    sm2 += rs[w][r][4]; sd2 += rs[w][r][5];
                    sx2 += rs[w][r][6]; sn2 += rs[w][r][7];
                }
            }
            g[0] = sm1 * invL * invws; g[1] = sd1 * invws;
            g[2] = sx1 * invws;        g[3] = sn1 * invws;
            g[4] = sm2 * invL * invws; g[5] = sd2 * invws;
            g[6] = sx2 * invws;        g[7] = sn2 * invws;
        }

        float h1;
        {
            float v = shB1[s][lane];
            #pragma unroll
            for (int f = 0; f < 8; f++) v = fmaf(shW1T[s][f][lane], g[f], v);
            h1 = fmaxf(v, 0.f);
        }
        float h2;
        {
            const int oo = lane & 15;
            float v = shB2[s][oo];
            #pragma unroll
            for (int f = 0; f < 32; f++)
                v = fmaf(shW2T[s][f][oo], __shfl_sync(0xffffffffu, h1, f), v);
            h2 = fmaxf(v, 0.f);
        }
        {
            float part = (lane < 16) ? shW3[s][lane] * h2 : 0.f;
            #pragma unroll
            for (int off = 16; off > 0; off >>= 1)
                part += __shfl_xor_sync(0xffffffffu, part, off);
            float z = __shfl_sync(0xffffffffu, part, 0) + shB3[s];
            float alpha = 1.0f / (1.0f + __expf(-z));
            if (lane >= r0 && lane < r0 + ws)
                acc = fmaf(wgt, alpha, acc);
        }
    }

    if (lane < 8)
        out[row0 + lane] = acc;
}

extern "C" void kernel_launch(void* const* d_in, const int* in_sizes, int n_in,
                              void* d_out, int out_size) {
    const float* a1 = (const float*)d_in[0];
    const float* a2 = (const float*)d_in[1];
    const float* W1 = (const float*)d_in[2];
    const float* b1 = (const float*)d_in[3];
    const float* W2 = (const float*)d_in[4];
    const float* b2 = (const float*)d_in[5];
    const float* W3 = (const float*)d_in[6];
    const float* b3 = (const float*)d_in[7];
    const float* sw = (const float*)d_in[8];
    float* out = (float*)d_out;

    const int dyn_smem = 8 * 3 * 1024 * (int)sizeof(float);   // 96KB
    cudaFuncSetAttribute(msdfg_kernel,
                         cudaFuncAttributeMaxDynamicSharedMemorySize, dyn_smem);

    const int groups = out_size / 8;     // 8192
    const int grid   = groups / 8;       // 1024 blocks, 8 warps each
    msdfg_kernel<<<grid, 256, dyn_smem>>>(a1, a2, W1, b1, W2, b2, W3, b3, sw, out);
}